// round 3
// baseline (speedup 1.0000x reference)
#include <cuda_runtime.h>
#include <math.h>

// ---------------------------------------------------------------------------
// Problem constants
// ---------------------------------------------------------------------------
#define NM_MAX 50000
#define ND_MAX 20000
#define FEAT   128

// Scratch (device globals: allocation-free rule)
__device__ float g_agg1 [(size_t)NM_MAX * FEAT];
__device__ float g_movie[(size_t)NM_MAX * FEAT];
__device__ float g_agg2 [(size_t)ND_MAX * FEAT];
__device__ float g_user1[(size_t)ND_MAX * FEAT];
__device__ float g_agg3 [(size_t)ND_MAX * FEAT];
__device__ float g_user2[(size_t)ND_MAX * FEAT];

// ---------------------------------------------------------------------------
// Helpers: packed f32x2 FMA (full-rate fp32 on sm_103a)
// ---------------------------------------------------------------------------
__device__ __forceinline__ void ffma2(unsigned long long& acc,
                                      unsigned long long a,
                                      unsigned long long b) {
    asm("fma.rn.f32x2 %0, %1, %2, %3;" : "=l"(acc) : "l"(a), "l"(b), "l"(acc));
}
__device__ __forceinline__ unsigned long long pack2(float lo, float hi) {
    unsigned long long r;
    asm("mov.b64 %0, {%1, %2};" : "=l"(r) : "f"(lo), "f"(hi));
    return r;
}

// ---------------------------------------------------------------------------
// Zero the three aggregation buffers
// ---------------------------------------------------------------------------
__global__ __launch_bounds__(256) void zero_aggs(int n_m, int n_d) {
    int i = blockIdx.x * 256 + threadIdx.x;
    float4 z = make_float4(0.f, 0.f, 0.f, 0.f);
    if (i < n_m * (FEAT / 4)) reinterpret_cast<float4*>(g_agg1)[i] = z;
    if (i < n_d * (FEAT / 4)) {
        reinterpret_cast<float4*>(g_agg2)[i] = z;
        reinterpret_cast<float4*>(g_agg3)[i] = z;
    }
}

// ---------------------------------------------------------------------------
// Edge scatter: one warp per edge. Gather 128-float row (1 float4/lane),
// optionally scale by sigmoid(edge_weight), vector-reduce into agg[dst].
// red.global.add.v4.f32 = no-return reduction, 4 floats/op: 4x fewer atomic
// ops than scalar atomicAdd and no return path through the LSU.
// ---------------------------------------------------------------------------
template <bool WEIGHTED>
__global__ __launch_bounds__(256)
void scatter_add_kernel(const float* __restrict__ x,
                        const int*   __restrict__ src,
                        const int*   __restrict__ dst,
                        const float* __restrict__ ew,
                        float*       __restrict__ agg,
                        int E) {
    int e = blockIdx.x * 8 + (threadIdx.x >> 5);
    if (e >= E) return;
    int lane = threadIdx.x & 31;
    int s = __ldg(src + e);
    int d = __ldg(dst + e);
    float4 v = *reinterpret_cast<const float4*>(x + (size_t)s * FEAT + lane * 4);
    if (WEIGHTED) {
        float w = 1.f / (1.f + __expf(-__ldg(ew + e)));
        v.x *= w; v.y *= w; v.z *= w; v.w *= w;
    }
    float* p = agg + (size_t)d * FEAT + lane * 4;
    asm volatile("red.global.add.v4.f32 [%0], {%1,%2,%3,%4};"
                 :: "l"(p), "f"(v.x), "f"(v.y), "f"(v.z), "f"(v.w) : "memory");
}

// ---------------------------------------------------------------------------
// Fused GraphConv GEMM:
//   out[m,n] = act( A1[m,:]@W1[:,n] + (HAS2 ? A2[m,:]@W2[:,n] : 0) + bias[n] )
// K = 128 fixed. BM=128, BK=8, 256 threads, thread tile 8 x TN, BN = 16*TN.
// Inner loop uses packed fma.rn.f32x2 (2 FMAs/instr) for full fp32 rate.
// ---------------------------------------------------------------------------
template <int BN, int TN, bool HAS2, bool RELU>
__global__ __launch_bounds__(256)
void gemm_fused(const float* __restrict__ A1, const float* __restrict__ W1,
                const float* __restrict__ A2, const float* __restrict__ W2,
                const float* __restrict__ bias,
                float* __restrict__ out, int M) {
    constexpr int BM = 128, BK = 8, K = 128, TM = 8;
    static_assert(BN == 16 * TN, "layout");

    __shared__ float sA[BK][BM + 4];
    __shared__ float sB[BK][BN];

    const int t = threadIdx.x;
    const int rowBase = blockIdx.x * BM;
    const int tm0 = (t / 16) * TM;
    const int tn0 = (t % 16) * TN;

    unsigned long long acc[TM][TN / 2] = {};  // 0 == {+0.f,+0.f}

    const int npair = HAS2 ? 2 : 1;
#pragma unroll 1
    for (int pair = 0; pair < npair; ++pair) {
        const float* A = (HAS2 && pair) ? A2 : A1;
        const float* W = (HAS2 && pair) ? W2 : W1;
#pragma unroll 1
        for (int kt = 0; kt < K; kt += BK) {
            // --- load A tile (BM x BK), transposed into sA[k][row] ---
            {
                int r  = t >> 1;
                int kk = (t & 1) * 4;
                float4 va = make_float4(0.f, 0.f, 0.f, 0.f);
                int gr = rowBase + r;
                if (gr < M)
                    va = *reinterpret_cast<const float4*>(A + (size_t)gr * K + kt + kk);
                sA[kk + 0][r] = va.x;
                sA[kk + 1][r] = va.y;
                sA[kk + 2][r] = va.z;
                sA[kk + 3][r] = va.w;
            }
            // --- load B tile (BK x BN) ---
            if (t < 2 * BN) {  // BK*BN/4 float4 loads
                int kr = t / (BN / 4);
                int nc = (t % (BN / 4)) * 4;
                *reinterpret_cast<float4*>(&sB[kr][nc]) =
                    *reinterpret_cast<const float4*>(W + (size_t)(kt + kr) * BN + nc);
            }
            __syncthreads();

#pragma unroll
            for (int k = 0; k < BK; ++k) {
                float4 a0 = *reinterpret_cast<const float4*>(&sA[k][tm0]);
                float4 a1 = *reinterpret_cast<const float4*>(&sA[k][tm0 + 4]);
                float av[TM] = {a0.x, a0.y, a0.z, a0.w, a1.x, a1.y, a1.z, a1.w};
                unsigned long long bv[TN / 2];
                const unsigned long long* bRow =
                    reinterpret_cast<const unsigned long long*>(&sB[k][tn0]);
#pragma unroll
                for (int j = 0; j < TN / 2; ++j) bv[j] = bRow[j];
#pragma unroll
                for (int i = 0; i < TM; ++i) {
                    unsigned long long ap = pack2(av[i], av[i]);
#pragma unroll
                    for (int j = 0; j < TN / 2; ++j) ffma2(acc[i][j], ap, bv[j]);
                }
            }
            __syncthreads();
        }
    }

    // --- epilogue: bias (+ReLU) + store ---
#pragma unroll
    for (int i = 0; i < TM; ++i) {
        int gr = rowBase + tm0 + i;
        if (gr < M) {
#pragma unroll
            for (int j = 0; j < TN / 2; ++j) {
                float2 v = *reinterpret_cast<float2*>(&acc[i][j]);
                float o0 = v.x + bias[tn0 + 2 * j];
                float o1 = v.y + bias[tn0 + 2 * j + 1];
                if (RELU) { o0 = fmaxf(o0, 0.f); o1 = fmaxf(o1, 0.f); }
                out[(size_t)gr * BN + tn0 + 2 * j]     = o0;
                out[(size_t)gr * BN + tn0 + 2 * j + 1] = o1;
            }
        }
    }
}

// ---------------------------------------------------------------------------
// Launch
// ---------------------------------------------------------------------------
extern "C" void kernel_launch(void* const* d_in, const int* in_sizes, int n_in,
                              void* d_out, int out_size) {
    const float* x_meas  = (const float*)d_in[0];
    const float* x_dem   = (const float*)d_in[1];
    const int*   src_m   = (const int*)  d_in[2];
    const int*   dst_m   = (const int*)  d_in[3];
    const int*   src_b   = (const int*)  d_in[4];
    const int*   dst_b   = (const int*)  d_in[5];
    const float* eweight = (const float*)d_in[6];
    const float* W_rel1  = (const float*)d_in[7];
    const float* b_rel1  = (const float*)d_in[8];
    const float* W_root1 = (const float*)d_in[9];
    const float* W_rel2  = (const float*)d_in[10];
    const float* b_rel2  = (const float*)d_in[11];
    const float* W_root2 = (const float*)d_in[12];
    const float* W_rel3  = (const float*)d_in[13];
    const float* b_rel3  = (const float*)d_in[14];
    const float* W_root3 = (const float*)d_in[15];
    const float* W_lin   = (const float*)d_in[16];
    const float* b_lin   = (const float*)d_in[17];
    float* out = (float*)d_out;

    const int n_m = in_sizes[0] / FEAT;
    const int n_d = in_sizes[1] / FEAT;
    const int E   = in_sizes[2];

    float *agg1, *agg2, *agg3, *movie, *user1, *user2;
    cudaGetSymbolAddress((void**)&agg1,  g_agg1);
    cudaGetSymbolAddress((void**)&agg2,  g_agg2);
    cudaGetSymbolAddress((void**)&agg3,  g_agg3);
    cudaGetSymbolAddress((void**)&movie, g_movie);
    cudaGetSymbolAddress((void**)&user1, g_user1);
    cudaGetSymbolAddress((void**)&user2, g_user2);

    const int edge_blocks = (E + 7) / 8;
    const int zero_elems  = (n_m > n_d ? n_m : n_d) * (FEAT / 4);

    // 1. zero aggregation buffers
    zero_aggs<<<(zero_elems + 255) / 256, 256>>>(n_m, n_d);

    // 2. scatter x_meas -> agg1 (movie graph, unweighted)
    scatter_add_kernel<false><<<edge_blocks, 256>>>(x_meas, src_m, dst_m, nullptr, agg1, E);

    // 3. scatter x_meas -> agg2 (bipartite, sigmoid-weighted)
    scatter_add_kernel<true><<<edge_blocks, 256>>>(x_meas, src_b, dst_b, eweight, agg2, E);

    // 4. movie_x = relu(agg1 @ W_rel1 + x_meas @ W_root1 + b_rel1)
    gemm_fused<128, 8, true, true><<<(n_m + 127) / 128, 256>>>(
        agg1, W_rel1, x_meas, W_root1, b_rel1, movie, n_m);

    // 5. user1 = relu(agg2 @ W_rel2 + x_dem @ W_root2 + b_rel2)
    gemm_fused<128, 8, true, true><<<(n_d + 127) / 128, 256>>>(
        agg2, W_rel2, x_dem, W_root2, b_rel2, user1, n_d);

    // 6. scatter movie_x -> agg3 (bipartite, sigmoid-weighted)
    scatter_add_kernel<true><<<edge_blocks, 256>>>(movie, src_b, dst_b, eweight, agg3, E);

    // 7. user2 = relu(agg3 @ W_rel3 + user1 @ W_root3 + b_rel3)
    gemm_fused<128, 8, true, true><<<(n_d + 127) / 128, 256>>>(
        agg3, W_rel3, user1, W_root3, b_rel3, user2, n_d);

    // 8. out = user2 @ W_lin + b_lin
    gemm_fused<64, 4, false, false><<<(n_d + 127) / 128, 256>>>(
        user2, W_lin, nullptr, nullptr, b_lin, out, n_d);
}

// round 5
// speedup vs baseline: 1.0093x; 1.0093x over previous
#include <cuda_runtime.h>
#include <math.h>
#include <string.h>

// ---------------------------------------------------------------------------
// Problem constants
// ---------------------------------------------------------------------------
#define NM_MAX 50000
#define ND_MAX 20000
#define EMAX   700000
#define FEAT   128

// Scratch (device globals: allocation-free rule)
__device__ float g_agg1 [(size_t)NM_MAX * FEAT];
__device__ float g_movie[(size_t)NM_MAX * FEAT];
__device__ float g_agg2 [(size_t)ND_MAX * FEAT];
__device__ float g_user1[(size_t)ND_MAX * FEAT];
__device__ float g_agg3 [(size_t)ND_MAX * FEAT];
__device__ float g_user2[(size_t)ND_MAX * FEAT];

// CSR-build scratch
__device__ int   g_cnt_m[NM_MAX + 1];
__device__ int   g_off_m[NM_MAX + 1];
__device__ int   g_cur_m[NM_MAX];
__device__ int   g_perm_m[EMAX];
__device__ int   g_cnt_b[ND_MAX + 1];
__device__ int   g_off_b[ND_MAX + 1];
__device__ int   g_cur_b[ND_MAX];
__device__ int   g_perm_b[EMAX];
__device__ float g_ews[EMAX];          // sigmoid(edge_weight)

// ---------------------------------------------------------------------------
// Helpers: packed f32x2 FMA (full-rate fp32 on sm_103a)
// ---------------------------------------------------------------------------
__device__ __forceinline__ void ffma2(unsigned long long& acc,
                                      unsigned long long a,
                                      unsigned long long b) {
    asm("fma.rn.f32x2 %0, %1, %2, %3;" : "=l"(acc) : "l"(a), "l"(b), "l"(acc));
}
__device__ __forceinline__ unsigned long long pack2(float lo, float hi) {
    unsigned long long r;
    asm("mov.b64 %0, {%1, %2};" : "=l"(r) : "f"(lo), "f"(hi));
    return r;
}

// ---------------------------------------------------------------------------
// CSR build step 1: zero histograms
// ---------------------------------------------------------------------------
__global__ __launch_bounds__(256) void zero_counts() {
    int i = blockIdx.x * 256 + threadIdx.x;
    if (i <= NM_MAX) g_cnt_m[i] = 0;
    if (i <= ND_MAX) g_cnt_b[i] = 0;
}

// Step 2: histogram both graphs + precompute sigmoid(ew)
__global__ __launch_bounds__(256)
void hist_kernel(const int* __restrict__ dst_m, const int* __restrict__ dst_b,
                 const float* __restrict__ ew, int E) {
    int e = blockIdx.x * 256 + threadIdx.x;
    if (e >= E) return;
    atomicAdd(&g_cnt_m[__ldg(dst_m + e)], 1);
    atomicAdd(&g_cnt_b[__ldg(dst_b + e)], 1);
    g_ews[e] = 1.f / (1.f + __expf(-__ldg(ew + e)));
}

// Step 3: single-block exclusive scan (n <= 50000), writes offs[0..n] and cur[0..n)
__global__ __launch_bounds__(1024)
void scan_kernel(const int* __restrict__ cnt, int* __restrict__ offs,
                 int* __restrict__ cur, int n) {
    __shared__ int ssum[1024];
    const int t = threadIdx.x;
    const int chunk = (n + 1023) / 1024;
    const int lo = t * chunk;
    const int hi = min(lo + chunk, n);
    int s = 0;
    for (int i = lo; i < hi; ++i) s += cnt[i];
    ssum[t] = s;
    __syncthreads();
    for (int off = 1; off < 1024; off <<= 1) {
        int tmp = (t >= off) ? ssum[t - off] : 0;
        __syncthreads();
        ssum[t] += tmp;
        __syncthreads();
    }
    int run = ssum[t] - s;   // exclusive base for this thread's chunk
    for (int i = lo; i < hi; ++i) {
        offs[i] = run;
        cur[i]  = run;
        run += cnt[i];
    }
    if (t == 0) offs[n] = ssum[1023];
}

// Step 4: fill edge-id permutations for both graphs
__global__ __launch_bounds__(256)
void fill_kernel(const int* __restrict__ dst_m, const int* __restrict__ dst_b, int E) {
    int e = blockIdx.x * 256 + threadIdx.x;
    if (e >= E) return;
    int p = atomicAdd(&g_cur_m[__ldg(dst_m + e)], 1);
    g_perm_m[p] = e;
    int q = atomicAdd(&g_cur_b[__ldg(dst_b + e)], 1);
    g_perm_b[q] = e;
}

// ---------------------------------------------------------------------------
// Gather-based aggregation: one warp per dst node. Edge meta loaded in
// chunks of 32 (lane-parallel, coalesced), broadcast via shfl; each lane
// accumulates 4 of the 128 features. No atomics, agg fully overwritten.
// ---------------------------------------------------------------------------
template <bool WEIGHTED>
__global__ __launch_bounds__(256)
void agg_gather(const float* __restrict__ x,
                const int*   __restrict__ src,
                const int*   __restrict__ perm,
                const int*   __restrict__ offs,
                float*       __restrict__ agg,
                int n_dst) {
    int d = blockIdx.x * 8 + (threadIdx.x >> 5);
    if (d >= n_dst) return;
    const int lane  = threadIdx.x & 31;
    const int start = __ldg(offs + d);
    const int end   = __ldg(offs + d + 1);

    float4 acc = make_float4(0.f, 0.f, 0.f, 0.f);
    for (int base = start; base < end; base += 32) {
        int i = base + lane;
        int e = (i < end) ? __ldg(perm + i) : 0;
        int s = (i < end) ? __ldg(src + e) : 0;
        float w = 1.f;
        if (WEIGHTED) w = (i < end) ? __ldg(g_ews + e) : 0.f;
        int cnt = min(32, end - base);
#pragma unroll 4
        for (int j = 0; j < cnt; ++j) {
            int   sj = __shfl_sync(0xffffffffu, s, j);
            float wj = WEIGHTED ? __shfl_sync(0xffffffffu, w, j) : 1.f;
            float4 v = *reinterpret_cast<const float4*>(x + (size_t)sj * FEAT + lane * 4);
            if (WEIGHTED) {
                acc.x = fmaf(wj, v.x, acc.x);
                acc.y = fmaf(wj, v.y, acc.y);
                acc.z = fmaf(wj, v.z, acc.z);
                acc.w = fmaf(wj, v.w, acc.w);
            } else {
                acc.x += v.x; acc.y += v.y; acc.z += v.z; acc.w += v.w;
            }
        }
    }
    *reinterpret_cast<float4*>(agg + (size_t)d * FEAT + lane * 4) = acc;
}

// ---------------------------------------------------------------------------
// Fused GraphConv GEMM, double-buffered smem pipeline, 1 sync per k-tile:
//   out[m,n] = act( A1[m,:]@W1[:,n] + (HAS2 ? A2[m,:]@W2[:,n] : 0) + bias[n] )
// K=128 per pass, BM=128, BK=8, 256 threads, thread tile 8 x TN, BN=16*TN.
// ---------------------------------------------------------------------------
template <int BN, int TN, bool HAS2, bool RELU>
__global__ __launch_bounds__(256)
void gemm_fused(const float* __restrict__ A1, const float* __restrict__ W1,
                const float* __restrict__ A2, const float* __restrict__ W2,
                const float* __restrict__ bias,
                float* __restrict__ out, int M) {
    constexpr int BM = 128, BK = 8, K = 128, TM = 8;
    constexpr int TPP = K / BK;                 // tiles per pass = 16
    constexpr int NT  = HAS2 ? 2 * TPP : TPP;   // total k-tiles
    static_assert(BN == 16 * TN, "layout");

    __shared__ float sA[2][BK][BM + 4];
    __shared__ float sB[2][BK][BN + 4];

    const int t = threadIdx.x;
    const int rowBase = blockIdx.x * BM;
    const int tm0 = (t / 16) * TM;
    const int tn0 = (t % 16) * TN;

    // A-load mapping: one float4 per thread
    const int ar  = t >> 1;
    const int akk = (t & 1) * 4;
    const int agr = rowBase + ar;
    // B-load mapping: one float4 per active thread
    const bool bact = t < (BK * BN / 4);
    const int  bkr  = t / (BN / 4);
    const int  bnc  = (t % (BN / 4)) * 4;

    float4 ra, rb;
    auto loadRegs = [&](int tt) {
        const float* A = (HAS2 && tt >= TPP) ? A2 : A1;
        const float* W = (HAS2 && tt >= TPP) ? W2 : W1;
        const int kt = (HAS2 ? (tt % TPP) : tt) * BK;
        ra = make_float4(0.f, 0.f, 0.f, 0.f);
        if (agr < M)
            ra = *reinterpret_cast<const float4*>(A + (size_t)agr * K + kt + akk);
        if (bact)
            rb = *reinterpret_cast<const float4*>(W + (size_t)(kt + bkr) * BN + bnc);
    };
    auto storeRegs = [&](int buf) {
        sA[buf][akk + 0][ar] = ra.x;
        sA[buf][akk + 1][ar] = ra.y;
        sA[buf][akk + 2][ar] = ra.z;
        sA[buf][akk + 3][ar] = ra.w;
        if (bact)
            *reinterpret_cast<float4*>(&sB[buf][bkr][bnc]) = rb;
    };

    unsigned long long acc[TM][TN / 2] = {};  // 0 == {+0.f,+0.f}

    loadRegs(0);
    storeRegs(0);
    __syncthreads();

#pragma unroll 1
    for (int tt = 0; tt < NT; ++tt) {
        const int cur = tt & 1;
        if (tt + 1 < NT) loadRegs(tt + 1);

        const float (*pA)[BM + 4] = sA[cur];
        const float (*pB)[BN + 4] = sB[cur];
#pragma unroll
        for (int k = 0; k < BK; ++k) {
            float4 a0 = *reinterpret_cast<const float4*>(&pA[k][tm0]);
            float4 a1 = *reinterpret_cast<const float4*>(&pA[k][tm0 + 4]);
            float av[TM] = {a0.x, a0.y, a0.z, a0.w, a1.x, a1.y, a1.z, a1.w};
            float4 bt[TN / 4];
#pragma unroll
            for (int jj = 0; jj < TN / 4; ++jj)
                bt[jj] = *reinterpret_cast<const float4*>(&pB[k][tn0 + 4 * jj]);
            unsigned long long bv[TN / 2];
            memcpy(bv, bt, sizeof(bt));
#pragma unroll
            for (int i = 0; i < TM; ++i) {
                unsigned long long ap = pack2(av[i], av[i]);
#pragma unroll
                for (int j = 0; j < TN / 2; ++j) ffma2(acc[i][j], ap, bv[j]);
            }
        }

        if (tt + 1 < NT) {
            storeRegs(cur ^ 1);
            __syncthreads();
        }
    }

    // --- epilogue: bias (+ReLU) + store ---
#pragma unroll
    for (int i = 0; i < TM; ++i) {
        int gr = rowBase + tm0 + i;
        if (gr < M) {
#pragma unroll
            for (int j = 0; j < TN / 2; ++j) {
                float2 v;
                memcpy(&v, &acc[i][j], 8);
                float o0 = v.x + bias[tn0 + 2 * j];
                float o1 = v.y + bias[tn0 + 2 * j + 1];
                if (RELU) { o0 = fmaxf(o0, 0.f); o1 = fmaxf(o1, 0.f); }
                out[(size_t)gr * BN + tn0 + 2 * j]     = o0;
                out[(size_t)gr * BN + tn0 + 2 * j + 1] = o1;
            }
        }
    }
}

// ---------------------------------------------------------------------------
// Launch
// ---------------------------------------------------------------------------
extern "C" void kernel_launch(void* const* d_in, const int* in_sizes, int n_in,
                              void* d_out, int out_size) {
    const float* x_meas  = (const float*)d_in[0];
    const float* x_dem   = (const float*)d_in[1];
    const int*   src_m   = (const int*)  d_in[2];
    const int*   dst_m   = (const int*)  d_in[3];
    const int*   src_b   = (const int*)  d_in[4];
    const int*   dst_b   = (const int*)  d_in[5];
    const float* eweight = (const float*)d_in[6];
    const float* W_rel1  = (const float*)d_in[7];
    const float* b_rel1  = (const float*)d_in[8];
    const float* W_root1 = (const float*)d_in[9];
    const float* W_rel2  = (const float*)d_in[10];
    const float* b_rel2  = (const float*)d_in[11];
    const float* W_root2 = (const float*)d_in[12];
    const float* W_rel3  = (const float*)d_in[13];
    const float* b_rel3  = (const float*)d_in[14];
    const float* W_root3 = (const float*)d_in[15];
    const float* W_lin   = (const float*)d_in[16];
    const float* b_lin   = (const float*)d_in[17];
    float* out = (float*)d_out;

    const int n_m = in_sizes[0] / FEAT;
    const int n_d = in_sizes[1] / FEAT;
    const int E   = in_sizes[2];

    float *agg1, *agg2, *agg3, *movie, *user1, *user2;
    cudaGetSymbolAddress((void**)&agg1,  g_agg1);
    cudaGetSymbolAddress((void**)&agg2,  g_agg2);
    cudaGetSymbolAddress((void**)&agg3,  g_agg3);
    cudaGetSymbolAddress((void**)&movie, g_movie);
    cudaGetSymbolAddress((void**)&user1, g_user1);
    cudaGetSymbolAddress((void**)&user2, g_user2);
    int *cnt_m, *off_m, *cur_m, *perm_m, *cnt_b, *off_b, *cur_b, *perm_b;
    cudaGetSymbolAddress((void**)&cnt_m,  g_cnt_m);
    cudaGetSymbolAddress((void**)&off_m,  g_off_m);
    cudaGetSymbolAddress((void**)&cur_m,  g_cur_m);
    cudaGetSymbolAddress((void**)&perm_m, g_perm_m);
    cudaGetSymbolAddress((void**)&cnt_b,  g_cnt_b);
    cudaGetSymbolAddress((void**)&off_b,  g_off_b);
    cudaGetSymbolAddress((void**)&cur_b,  g_cur_b);
    cudaGetSymbolAddress((void**)&perm_b, g_perm_b);

    const int eb = (E + 255) / 256;

    // --- CSR build (both graphs) ---
    zero_counts<<<(NM_MAX + 256) / 256, 256>>>();
    hist_kernel<<<eb, 256>>>(dst_m, dst_b, eweight, E);
    scan_kernel<<<1, 1024>>>(cnt_m, off_m, cur_m, n_m);
    scan_kernel<<<1, 1024>>>(cnt_b, off_b, cur_b, n_d);
    fill_kernel<<<eb, 256>>>(dst_m, dst_b, E);

    // --- Layer 1 aggregations (gather, no atomics) ---
    agg_gather<false><<<(n_m + 7) / 8, 256>>>(x_meas, src_m, perm_m, off_m, agg1, n_m);
    agg_gather<true ><<<(n_d + 7) / 8, 256>>>(x_meas, src_b, perm_b, off_b, agg2, n_d);

    // --- Layer 1/2 GEMMs ---
    gemm_fused<128, 8, true, true><<<(n_m + 127) / 128, 256>>>(
        agg1, W_rel1, x_meas, W_root1, b_rel1, movie, n_m);
    gemm_fused<128, 8, true, true><<<(n_d + 127) / 128, 256>>>(
        agg2, W_rel2, x_dem, W_root2, b_rel2, user1, n_d);

    // --- Layer 3 aggregation (reuses bipartite CSR) + GEMM ---
    agg_gather<true><<<(n_d + 7) / 8, 256>>>(movie, src_b, perm_b, off_b, agg3, n_d);
    gemm_fused<128, 8, true, true><<<(n_d + 127) / 128, 256>>>(
        agg3, W_rel3, user1, W_root3, b_rel3, user2, n_d);

    // --- Output projection ---
    gemm_fused<64, 4, false, false><<<(n_d + 127) / 128, 256>>>(
        user2, W_lin, nullptr, nullptr, b_lin, out, n_d);
}